// round 17
// baseline (speedup 1.0000x reference)
#include <cuda_runtime.h>
#include <cstdint>

// ---------------------------------------------------------------------------
// B=4096, Te=168, Td=24, X=8, H=64; 3-layer LSTM, gate order i,f,g,o.
// Gate-split SIMT formulation:
//   One CTA = 32 batch elements, 512 threads (16 warps, barrier-convoyed).
//   Thread t: e = t&1 (e=0 -> gates i,f ; e=1 -> gates g,o),
//             h = (t>>1)&63, 8-batch slice bs = (t>>7)*8.
//   Pointwise LSTM coupling via two __shfl_xor(.,1) exchanges (same warp).
//   grid=128, 1 CTA/SM, 4 warps/SMSP. Cell state in registers (e=0 lanes);
//   hidden state double-buffered in SMEM; weights LDG.128 depth-1 pipeline.
// ---------------------------------------------------------------------------
#define HH      64
#define BT      32
#define NTHR    512
#define TE      168
#define TD      24
#define XDIM    8
#define BTOT    4096

typedef unsigned long long ull;

// Contiguous weight rows (one row = one jb block = 4 j-values x 4 gates x 64 h
// = 256 float4 = 4KB):
//   L0: rows  0..17  (j 0..7 = x, j 8..71 = h0_prev)
//   L1: rows 18..49  (j 0..63 = h0_cur, 64..127 = h1_prev)
//   L2: rows 50..81  (j 0..63 = h1_cur, 64..127 = h2_prev)
//   rows 82..83 = zero pads (depth-1 prefetch overrun)
#define NROWS   84
__device__ float4 g_W4[NROWS * 256];

// ---------------------------------------------------------------------------
// f32x2 dual-FMA helpers
// ---------------------------------------------------------------------------
__device__ __forceinline__ ull ffma2(ull a, ull b, ull c) {
    ull d;
    asm("fma.rn.f32x2 %0, %1, %2, %3;" : "=l"(d) : "l"(a), "l"(b), "l"(c));
    return d;
}
__device__ __forceinline__ ull pack2(float lo, float hi) {
    ull d;
    asm("mov.b64 %0, {%1, %2};" : "=l"(d) : "f"(lo), "f"(hi));
    return d;
}
__device__ __forceinline__ float2 unpack2(ull v) {
    float lo, hi;
    asm("mov.b64 {%0, %1}, %2;" : "=f"(lo), "=f"(hi) : "l"(v));
    return make_float2(lo, hi);
}

__device__ __forceinline__ float fast_sigmoid(float x) {
    float e;
    asm("ex2.approx.f32 %0, %1;" : "=f"(e) : "f"(-1.4426950408889634f * x));
    float r;
    asm("rcp.approx.f32 %0, %1;" : "=f"(r) : "f"(1.0f + e));
    return r;
}
__device__ __forceinline__ float fast_tanh(float x) {
    return fmaf(2.0f, fast_sigmoid(2.0f * x), -1.0f);
}

// ---------------------------------------------------------------------------
// Weight prep into the contiguous layout.
// g_W4[(row*4 + q)*64 + h].component[f] = W_l[gate q*64+h][ j = jb*4+f ]
// ---------------------------------------------------------------------------
__global__ void prep_weights(const float* __restrict__ Wih0, const float* __restrict__ Whh0,
                             const float* __restrict__ Wih1, const float* __restrict__ Whh1,
                             const float* __restrict__ Wih2, const float* __restrict__ Whh2) {
    int idx = blockIdx.x * blockDim.x + threadIdx.x;
    const int total = NROWS * 256 * 4;
    if (idx >= total) return;
    int f   = idx & 3;
    int h   = (idx >> 2) & 63;
    int q   = (idx >> 8) & 3;
    int row = idx >> 10;
    int g   = q * 64 + h;
    float val = 0.0f;
    if (row < 18) {                    // L0
        int j = row * 4 + f;
        if (j < 8)       val = Wih0[g * 8 + j];
        else             val = Whh0[g * 64 + (j - 8)];
    } else if (row < 50) {             // L1
        int j = (row - 18) * 4 + f;
        val = (j < 64) ? Wih1[g * 64 + j] : Whh1[g * 64 + (j - 64)];
    } else if (row < 82) {             // L2
        int j = (row - 50) * 4 + f;
        val = (j < 64) ? Wih2[g * 64 + j] : Whh2[g * 64 + (j - 64)];
    }                                   // rows 82..83: pads -> 0
    reinterpret_cast<float*>(g_W4)[idx] = val;
}

// ---------------------------------------------------------------------------
// Accumulate NBLK 4-j blocks into acc[2][8] for this thread's 2 gates.
// Weights: 2x LDG.128 per block (this thread's gate rows), depth-1 register
// pipeline. Activations: warp-uniform LDS.128 broadcast.
// Per warp per block: 2 LDG wf + 8 LDS-broadcast + 32 FFMA2.
// ---------------------------------------------------------------------------
template <int NBLK, int STRIDE>
__device__ __forceinline__ void accum2(ull acc[2][8], const float4* __restrict__ wp,
                                       const float* __restrict__ sbase) {
    float4 w0 = __ldg(wp + 0);
    float4 w1 = __ldg(wp + 64);
#pragma unroll 2
    for (int blk = 0; blk < NBLK; blk++) {
        const float4* np = wp + (blk + 1) * 256;   // depth-1 (pads protect tail)
        float4 n0 = __ldg(np + 0);
        float4 n1 = __ldg(np + 64);

        ulonglong2 u0 = *reinterpret_cast<const ulonglong2*>(&w0);
        ulonglong2 u1 = *reinterpret_cast<const ulonglong2*>(&w1);
        const float* sp = sbase + blk * 4;
#pragma unroll
        for (int b = 0; b < 8; b++) {
            ulonglong2 a = *reinterpret_cast<const ulonglong2*>(sp + b * STRIDE);
            acc[0][b] = ffma2(u0.x, a.x, acc[0][b]);
            acc[1][b] = ffma2(u1.x, a.x, acc[1][b]);
            acc[0][b] = ffma2(u0.y, a.y, acc[0][b]);
            acc[1][b] = ffma2(u1.y, a.y, acc[1][b]);
        }
        w0 = n0; w1 = n1;
    }
}

// Dynamic SMEM layout (~50 KB)
struct Smem {
    float hbuf[3][2][BT][HH];   // double-buffered hidden state (48 KB)
    float x_s[2][BT][XDIM];     // double-buffered step input
    float z_s[BT];
    float vf_s[BT];
    float rvf_s[BT];
    float wm_s[HH];
    float wa_s[HH];
    float bm_ba[2];
};

// One 3-layer step, double-buffered hidden state (1 barrier per layer).
// Reads hb[l][pp] (prev step), writes hb[l][pp^1] (e=0 lanes store).
// e=0 accumulates gates i,f ; e=1 accumulates g,o. Two shfl_xor(.,1)
// exchanges recombine: e0 cn = f*c + i*g ; hv = o * tanh(cn).
__device__ __forceinline__ void step3(float (&c)[3][8], const float (&bias)[3][2],
                                      int e, int h, int bs, int pp,
                                      float (*hb)[2][BT][HH],
                                      const float (*x_s)[XDIM]) {
    const float mulc = e ? 2.0f : 1.0f;     // tanh-vs-sigmoid fold for slot 0
    const float addc = e ? -1.0f : 0.0f;
    const int   qoff = e * 128 + h;         // this thread's first gate row

#pragma unroll
    for (int l = 0; l < 3; l++) {
        ull acc[2][8];
#pragma unroll
        for (int q = 0; q < 2; q++) {
            ull z = pack2(bias[l][q], 0.0f);
#pragma unroll
            for (int k = 0; k < 8; k++) acc[q][k] = z;
        }

        if (l == 0) {
            accum2<2,  XDIM>(acc, g_W4 + 0 * 256 + qoff,  &x_s[bs][0]);
            accum2<16, HH  >(acc, g_W4 + 2 * 256 + qoff,  &hb[0][pp][bs][0]);
        } else if (l == 1) {
            accum2<16, HH  >(acc, g_W4 + 18 * 256 + qoff, &hb[0][pp ^ 1][bs][0]);
            accum2<16, HH  >(acc, g_W4 + 34 * 256 + qoff, &hb[1][pp][bs][0]);
        } else {
            accum2<16, HH  >(acc, g_W4 + 50 * 256 + qoff, &hb[1][pp ^ 1][bs][0]);
            accum2<16, HH  >(acc, g_W4 + 66 * 256 + qoff, &hb[2][pp][bs][0]);
        }

#pragma unroll
        for (int k = 0; k < 8; k++) {
            float2 s0 = unpack2(acc[0][k]);
            float2 s1 = unpack2(acc[1][k]);
            float x0 = s0.x + s0.y;                       // e0: pre-i, e1: pre-g
            float x1 = s1.x + s1.y;                       // e0: pre-f, e1: pre-o
            float g0 = fmaf(fast_sigmoid(x0 * mulc), mulc, addc);  // e0: i, e1: g
            float g1 = fast_sigmoid(x1);                  // e0: f, e1: o
            float gv = __shfl_xor_sync(0xffffffffu, g0, 1);        // e0 <- g
            float cn = fmaf(g1, c[l][k], g0 * gv);        // e0: f*c + i*g
            float th = fast_tanh(cn);
            float ov = __shfl_xor_sync(0xffffffffu, e ? g1 : th, 1); // e0 <- o
            if (!e) {
                c[l][k] = cn;
                hb[l][pp ^ 1][bs + k][h] = ov * th;
            }
        }
        __syncthreads();   // layer-l outputs visible; old buffer free
    }
}

// ---------------------------------------------------------------------------
// Main kernel: one CTA per 32-batch tile, whole encoder+decoder sequence.
// ---------------------------------------------------------------------------
__global__ void __launch_bounds__(NTHR, 1)
lstm_seq_kernel(const float* __restrict__ enc_x, const float* __restrict__ enc_z,
                const float* __restrict__ dec_x, const float* __restrict__ v,
                const float* __restrict__ eps,
                const float* __restrict__ b0, const float* __restrict__ b1,
                const float* __restrict__ b2,
                const float* __restrict__ w_m, const float* __restrict__ b_m,
                const float* __restrict__ w_a, const float* __restrict__ b_a,
                float* __restrict__ out) {
    extern __shared__ __align__(16) char smem_raw[];
    Smem& sm = *reinterpret_cast<Smem*>(smem_raw);

    const int t   = threadIdx.x;
    const int e   = t & 1;
    const int h   = (t >> 1) & 63;
    const int bs  = (t >> 7) * 8;    // 4 groups x 8 batches = 32
    const int b0g = blockIdx.x * BT;

    // this thread's 2 gate biases per layer (e0: i,f ; e1: g,o)
    float bias[3][2];
#pragma unroll
    for (int q = 0; q < 2; q++) {
        int g = (e * 2 + q) * 64 + h;
        bias[0][q] = b0[g];
        bias[1][q] = b1[g];
        bias[2][q] = b2[g];
    }

    for (int i = t; i < 3 * 2 * BT * HH; i += NTHR) (&sm.hbuf[0][0][0][0])[i] = 0.0f;
    if (t < HH) { sm.wm_s[t] = w_m[t]; sm.wa_s[t] = w_a[t]; }
    if (t == 0) { sm.bm_ba[0] = b_m[0]; sm.bm_ba[1] = b_a[0]; }

    float c[3][8];
#pragma unroll
    for (int l = 0; l < 3; l++)
#pragma unroll
        for (int k = 0; k < 8; k++) c[l][k] = 0.0f;

    const int bb = t >> 3, xi = t & 7;   // threads 0..255: 32x8 x-loader
    int pp = 0;

    // ---------------- encoder ----------------
    if (t < BT * XDIM)
        sm.x_s[0][bb][xi] = enc_x[(size_t)(b0g + bb) * (TE * XDIM) + 0 * XDIM + xi];
    __syncthreads();
    for (int s = 0; s < TE; s++) {
        int cur = s & 1;
        if (s + 1 < TE && t < BT * XDIM)
            sm.x_s[cur ^ 1][bb][xi] =
                enc_x[(size_t)(b0g + bb) * (TE * XDIM) + (s + 1) * XDIM + xi];
        step3(c, bias, e, h, bs, pp, sm.hbuf, sm.x_s[cur]);
        pp ^= 1;
    }

    // ---------------- decoder init ----------------
    if (t < BT) {
        float vf  = v[b0g + t];
        float rvf = 1.0f / vf;
        sm.vf_s[t]  = vf;
        sm.rvf_s[t] = rvf;
        sm.z_s[t]   = enc_z[(size_t)(b0g + t) * TE + (TE - 1)] * rvf;
    }
    __syncthreads();

    // ---------------- decoder ----------------
    for (int s = 0; s < TD; s++) {
        if (t < BT * XDIM) {
            float xv;
            if (xi == 0) xv = sm.z_s[bb];
            else xv = dec_x[(size_t)(b0g + bb) * (TD * (XDIM - 1)) + s * (XDIM - 1) + (xi - 1)];
            sm.x_s[0][bb][xi] = xv;
        }
        __syncthreads();

        step3(c, bias, e, h, bs, pp, sm.hbuf, sm.x_s[0]);

        if (t < BT) {
            float m  = sm.bm_ba[0];
            float ap = sm.bm_ba[1];
            const float* hrow = &sm.hbuf[2][pp ^ 1][t][0];
#pragma unroll
            for (int kk = 0; kk < HH; kk++) {
                int k = (kk + t) & 63;       // bank-conflict-free rotation
                float hv = hrow[k];
                m  = fmaf(hv, sm.wm_s[k], m);
                ap = fmaf(hv, sm.wa_s[k], ap);
            }
            float vf = sm.vf_s[t];
            m *= vf;
            float sp = fmaxf(ap, 0.0f) + log1pf(__expf(-fabsf(ap)));
            float a  = sp * vf;
            float zs = fmaf(a, eps[(size_t)(b0g + t) * TD + s], m);
            out[(size_t)(b0g + t) * TD + s] = zs;
            sm.z_s[t] = zs * sm.rvf_s[t];
        }
        pp ^= 1;
        __syncthreads();   // z_s ready before next step's x loader
    }
}

// ---------------------------------------------------------------------------
// Input order: enc_x, enc_z, dec_x, v, eps,
//   W_ih0, W_hh0, b0, W_ih1, W_hh1, b1, W_ih2, W_hh2, b2, w_m, b_m, w_a, b_a
// ---------------------------------------------------------------------------
extern "C" void kernel_launch(void* const* d_in, const int* in_sizes, int n_in,
                              void* d_out, int out_size) {
    (void)in_sizes; (void)n_in; (void)out_size;
    const float* enc_x = (const float*)d_in[0];
    const float* enc_z = (const float*)d_in[1];
    const float* dec_x = (const float*)d_in[2];
    const float* v     = (const float*)d_in[3];
    const float* eps   = (const float*)d_in[4];
    const float* Wih0  = (const float*)d_in[5];
    const float* Whh0  = (const float*)d_in[6];
    const float* b0    = (const float*)d_in[7];
    const float* Wih1  = (const float*)d_in[8];
    const float* Whh1  = (const float*)d_in[9];
    const float* b1    = (const float*)d_in[10];
    const float* Wih2  = (const float*)d_in[11];
    const float* Whh2  = (const float*)d_in[12];
    const float* b2    = (const float*)d_in[13];
    const float* w_m   = (const float*)d_in[14];
    const float* b_m   = (const float*)d_in[15];
    const float* w_a   = (const float*)d_in[16];
    const float* b_a   = (const float*)d_in[17];
    float* out = (float*)d_out;

    // >48KB dynamic smem: opt in (idempotent; capture-safe)
    cudaFuncSetAttribute(lstm_seq_kernel,
                         cudaFuncAttributeMaxDynamicSharedMemorySize,
                         (int)sizeof(Smem));

    const int total = NROWS * 256 * 4;
    prep_weights<<<(total + 255) / 256, 256>>>(Wih0, Whh0, Wih1, Whh1, Wih2, Whh2);
    lstm_seq_kernel<<<BTOT / BT, NTHR, sizeof(Smem)>>>(enc_x, enc_z, dec_x, v, eps,
                                                       b0, b1, b2, w_m, b_m, w_a, b_a, out);
}